// round 8
// baseline (speedup 1.0000x reference)
#include <cuda_runtime.h>
#include <cuda_bf16.h>
#include <limits.h>

#define H_HALF 4096
#define BLOCK 256
#define V4 4                  // 4 float4 = 16 floats per thread; 256*16 = 4096
#define NWARP (BLOCK / 32)
#define ROWS_PER_BLOCK 4
#define MAX_PARTIAL 2048      // 8192 half-rows / 4 rows per block

__device__ float g_partial[MAX_PARTIAL];
__device__ unsigned int g_counter = 0;

__global__ __launch_bounds__(BLOCK)
void pulse_loss_kernel(const float* __restrict__ pred,
                       const float* __restrict__ lab,
                       float* __restrict__ out,
                       float scale) {
    const int t = threadIdx.x;
    const int wid = t >> 5;
    const int lid = t & 31;

    __shared__ int s_first[NWARP];
    __shared__ int s_last[NWARP];
    __shared__ int s_bcast[2];
    __shared__ float s_sum[NWARP];
    __shared__ int s_is_last;

    const long row0 = (long)blockIdx.x * ROWS_PER_BLOCK;

    // Double-buffered row data
    float4 lbuf[2][V4];
    float4 pbuf[2][V4];

    // Prologue: load row 0 into buffer 0
    {
        const float4* l4 = (const float4*)(lab  + row0 * H_HALF);
        const float4* p4 = (const float4*)(pred + row0 * H_HALF);
        #pragma unroll
        for (int i = 0; i < V4; i++) lbuf[0][i] = __ldcs(&l4[t + i * BLOCK]);
        #pragma unroll
        for (int i = 0; i < V4; i++) pbuf[0][i] = __ldcs(&p4[t + i * BLOCK]);
    }

    float block_acc = 0.0f;   // valid on t==0 only

    #pragma unroll
    for (int r = 0; r < ROWS_PER_BLOCK; r++) {
        const int cur = r & 1;
        const int nxt = cur ^ 1;

        // Issue next row's loads BEFORE this row's barriers: they stay in
        // flight across the reduce, keeping DRAM busy.
        if (r + 1 < ROWS_PER_BLOCK) {
            const float4* l4 = (const float4*)(lab  + (row0 + r + 1) * H_HALF);
            const float4* p4 = (const float4*)(pred + (row0 + r + 1) * H_HALF);
            #pragma unroll
            for (int i = 0; i < V4; i++) lbuf[nxt][i] = __ldcs(&l4[t + i * BLOCK]);
            #pragma unroll
            for (int i = 0; i < V4; i++) pbuf[nxt][i] = __ldcs(&p4[t + i * BLOCK]);
        }

        // first/last significant index from current row's labels
        int firstI = INT_MAX;
        int lastI  = -1;
        #pragma unroll
        for (int i = 0; i < V4; i++) {
            const int gi = (t + i * BLOCK) * 4;
            const float4 l = lbuf[cur][i];
            if (fabsf(l.x) > 0.01f) { firstI = min(firstI, gi + 0); lastI = max(lastI, gi + 0); }
            if (fabsf(l.y) > 0.01f) { firstI = min(firstI, gi + 1); lastI = max(lastI, gi + 1); }
            if (fabsf(l.z) > 0.01f) { firstI = min(firstI, gi + 2); lastI = max(lastI, gi + 2); }
            if (fabsf(l.w) > 0.01f) { firstI = min(firstI, gi + 3); lastI = max(lastI, gi + 3); }
        }

        int wfirst = __reduce_min_sync(0xFFFFFFFFu, firstI);
        int wlast  = __reduce_max_sync(0xFFFFFFFFu, lastI);
        if (lid == 0) { s_first[wid] = wfirst; s_last[wid] = wlast; }
        __syncthreads();
        if (wid == 0) {
            int f  = (lid < NWARP) ? s_first[lid] : INT_MAX;
            int ll = (lid < NWARP) ? s_last[lid]  : -1;
            f  = __reduce_min_sync(0xFFFFFFFFu, f);
            ll = __reduce_max_sync(0xFFFFFFFFu, ll);
            if (lid == 0) {
                if (f == INT_MAX) { f = 0; ll = H_HALF - 1; }  // all-insignificant: fallback
                s_bcast[0] = f;
                s_bcast[1] = ll;
            }
        }
        __syncthreads();
        const int first = s_bcast[0];
        const int last  = s_bcast[1];

        // Weighted squared diffs
        float acc = 0.0f;
        #pragma unroll
        for (int i = 0; i < V4; i++) {
            const int gi = (t + i * BLOCK) * 4;
            const float4 l = lbuf[cur][i];
            const float4 p = pbuf[cur][i];
            const float d0 = p.x - l.x;
            const float d1 = p.y - l.y;
            const float d2 = p.z - l.z;
            const float d3 = p.w - l.w;
            const float w0 = (gi + 0 < first || gi + 0 > last) ? 2.0f : 1.0f;
            const float w1 = (gi + 1 < first || gi + 1 > last) ? 2.0f : 1.0f;
            const float w2 = (gi + 2 < first || gi + 2 > last) ? 2.0f : 1.0f;
            const float w3 = (gi + 3 < first || gi + 3 > last) ? 2.0f : 1.0f;
            acc += w0 * d0 * d0 + w1 * d1 * d1 + w2 * d2 * d2 + w3 * d3 * d3;
        }

        // Block reduce sum (deterministic)
        #pragma unroll
        for (int o = 16; o > 0; o >>= 1)
            acc += __shfl_xor_sync(0xFFFFFFFFu, acc, o);
        if (lid == 0) s_sum[wid] = acc;
        __syncthreads();
        if (t == 0) {
            float v = 0.0f;
            #pragma unroll
            for (int w = 0; w < NWARP; w++) v += s_sum[w];
            block_acc += v;
        }
        // s_sum is rewritten only after the two syncs of the next iteration,
        // so t0's read above is safe without an extra barrier.
    }

    if (t == 0) {
        g_partial[blockIdx.x] = block_acc;
        __threadfence();
        unsigned int done = atomicAdd(&g_counter, 1u);
        s_is_last = (done == gridDim.x - 1) ? 1 : 0;
    }
    __syncthreads();

    // Last block: deterministic final reduction over all partials
    if (s_is_last) {
        __threadfence();
        const int nparts = gridDim.x;
        float facc = 0.0f;
        for (int i = t; i < nparts; i += BLOCK)
            facc += __ldcg(&g_partial[i]);   // fixed order per thread -> deterministic

        #pragma unroll
        for (int o = 16; o > 0; o >>= 1)
            facc += __shfl_xor_sync(0xFFFFFFFFu, facc, o);
        if (lid == 0) s_sum[wid] = facc;
        __syncthreads();
        if (t == 0) {
            float v = 0.0f;
            #pragma unroll
            for (int w = 0; w < NWARP; w++) v += s_sum[w];
            out[0] = v * scale;
            g_counter = 0;   // reset for next graph replay
        }
    }
}

extern "C" void kernel_launch(void* const* d_in, const int* in_sizes, int n_in,
                              void* d_out, int out_size) {
    const float* pred = (const float*)d_in[0];
    const float* lab  = (const float*)d_in[1];
    float* out = (float*)d_out;

    const long n = in_sizes[0];          // total elements (B * N)
    const long half_rows = n / H_HALF;   // B * 2
    const long B = half_rows / 2;
    const float scale = 1.0f / ((float)B * (float)H_HALF);

    const unsigned grid = (unsigned)(half_rows / ROWS_PER_BLOCK);
    pulse_loss_kernel<<<grid, BLOCK>>>(pred, lab, out, scale);
}

// round 10
// speedup vs baseline: 1.0940x; 1.0940x over previous
#include <cuda_runtime.h>
#include <cuda_bf16.h>
#include <limits.h>
#include <stdint.h>

#define H_HALF 4096
#define BLOCK 256
#define NWARP (BLOCK / 32)
#define V4 4                       // 4 float4 per thread = 16 floats; 256*16 = 4096
#define D_STAGES 3
#define ROW_BYTES (H_HALF * 4)     // 16 KB per array per half-row
#define STAGE_BYTES (2 * ROW_BYTES) // 32 KB: [lab 16K][pred 16K]
#define MAX_GRID 296               // 2 blocks per SM on 148 SMs

__device__ float g_partial[MAX_GRID];
__device__ unsigned int g_counter = 0;

__device__ __forceinline__ uint32_t smem_u32(const void* p) {
    uint32_t a;
    asm("{ .reg .u64 tmp; cvta.to.shared.u64 tmp, %1; cvt.u32.u64 %0, tmp; }"
        : "=r"(a) : "l"(p));
    return a;
}

__device__ __forceinline__ void mbar_init(uint32_t mbar, uint32_t count) {
    asm volatile("mbarrier.init.shared.b64 [%0], %1;" :: "r"(mbar), "r"(count) : "memory");
}

__device__ __forceinline__ void mbar_expect_tx(uint32_t mbar, uint32_t bytes) {
    asm volatile("mbarrier.arrive.expect_tx.shared.b64 _, [%0], %1;"
                 :: "r"(mbar), "r"(bytes) : "memory");
}

__device__ __forceinline__ void bulk_g2s(uint32_t dst_smem, const void* src_gmem,
                                         uint32_t bytes, uint32_t mbar) {
    asm volatile(
        "cp.async.bulk.shared::cluster.global.mbarrier::complete_tx::bytes "
        "[%0], [%1], %2, [%3];"
        :: "r"(dst_smem), "l"(src_gmem), "r"(bytes), "r"(mbar) : "memory");
}

__device__ __forceinline__ void mbar_wait_parity(uint32_t mbar, uint32_t parity) {
    uint32_t done;
    asm volatile(
        "{\n\t"
        ".reg .pred p;\n\t"
        "mbarrier.try_wait.parity.acquire.cta.shared::cta.b64 p, [%1], %2;\n\t"
        "selp.b32 %0, 1, 0, p;\n\t"
        "}"
        : "=r"(done) : "r"(mbar), "r"(parity) : "memory");
    if (!done) {
        asm volatile(
            "{\n\t"
            ".reg .pred P1;\n\t"
            "WAIT_LOOP_%=:\n\t"
            "mbarrier.try_wait.parity.acquire.cta.shared::cta.b64 P1, [%0], %1, 0x989680;\n\t"
            "@P1 bra.uni WAIT_DONE_%=;\n\t"
            "bra.uni WAIT_LOOP_%=;\n\t"
            "WAIT_DONE_%=:\n\t"
            "}"
            :: "r"(mbar), "r"(parity) : "memory");
    }
}

extern __shared__ char dyn_smem[];   // D_STAGES * STAGE_BYTES

__global__ __launch_bounds__(BLOCK)
void pulse_loss_kernel(const float* __restrict__ pred,
                       const float* __restrict__ lab,
                       float* __restrict__ out,
                       float scale, int total_rows) {
    __shared__ uint64_t mbar_store[D_STAGES];
    __shared__ int s_first[NWARP];
    __shared__ int s_last[NWARP];
    __shared__ int s_bcast[2];
    __shared__ float s_sum[NWARP];
    __shared__ int s_is_last;

    const int t = threadIdx.x;
    const int wid = t >> 5;
    const int lid = t & 31;
    const int bid = blockIdx.x;
    const int G = gridDim.x;
    const int nk = (total_rows - bid + G - 1) / G;   // rows this block handles

    const uint32_t smem_base = smem_u32(dyn_smem);
    uint32_t mbar[D_STAGES];
    #pragma unroll
    for (int s = 0; s < D_STAGES; s++)
        mbar[s] = smem_u32(&mbar_store[s]);

    if (t == 0) {
        #pragma unroll
        for (int s = 0; s < D_STAGES; s++)
            mbar_init(mbar[s], 1);
        asm volatile("fence.proxy.async.shared::cta;" ::: "memory");
    }
    __syncthreads();

    // Prologue: fill pipeline with first D rows
    if (t == 0) {
        const int pmax = (D_STAGES < nk) ? D_STAGES : nk;
        for (int j = 0; j < pmax; j++) {
            const long rid = bid + (long)j * G;
            const uint32_t dst = smem_base + j * STAGE_BYTES;
            mbar_expect_tx(mbar[j], STAGE_BYTES);
            bulk_g2s(dst,             lab  + rid * H_HALF, ROW_BYTES, mbar[j]);
            bulk_g2s(dst + ROW_BYTES, pred + rid * H_HALF, ROW_BYTES, mbar[j]);
        }
    }

    float wacc = 0.0f;   // per-thread weighted sum across all rows (deterministic order)

    for (int k = 0; k < nk; k++) {
        const int s  = k % D_STAGES;
        const int ph = (k / D_STAGES) & 1;
        mbar_wait_parity(mbar[s], ph);

        const float4* slab  = (const float4*)(dyn_smem + s * STAGE_BYTES);
        const float4* spred = (const float4*)(dyn_smem + s * STAGE_BYTES + ROW_BYTES);

        // Phase A: labels -> registers, per-thread first/last
        float4 l[V4];
        #pragma unroll
        for (int i = 0; i < V4; i++)
            l[i] = slab[t + i * BLOCK];

        int firstI = INT_MAX;
        int lastI  = -1;
        #pragma unroll
        for (int i = 0; i < V4; i++) {
            const int gi = (t + i * BLOCK) * 4;
            if (fabsf(l[i].x) > 0.01f) { firstI = min(firstI, gi + 0); lastI = max(lastI, gi + 0); }
            if (fabsf(l[i].y) > 0.01f) { firstI = min(firstI, gi + 1); lastI = max(lastI, gi + 1); }
            if (fabsf(l[i].z) > 0.01f) { firstI = min(firstI, gi + 2); lastI = max(lastI, gi + 2); }
            if (fabsf(l[i].w) > 0.01f) { firstI = min(firstI, gi + 3); lastI = max(lastI, gi + 3); }
        }

        int wfirst = __reduce_min_sync(0xFFFFFFFFu, firstI);
        int wlast  = __reduce_max_sync(0xFFFFFFFFu, lastI);
        if (lid == 0) { s_first[wid] = wfirst; s_last[wid] = wlast; }
        __syncthreads();
        if (wid == 0) {
            int f  = (lid < NWARP) ? s_first[lid] : INT_MAX;
            int ll = (lid < NWARP) ? s_last[lid]  : -1;
            f  = __reduce_min_sync(0xFFFFFFFFu, f);
            ll = __reduce_max_sync(0xFFFFFFFFu, ll);
            if (lid == 0) {
                if (f == INT_MAX) { f = 0; ll = H_HALF - 1; }  // all-insignificant fallback
                s_bcast[0] = f;
                s_bcast[1] = ll;
            }
        }
        __syncthreads();
        const int first = s_bcast[0];
        const int last  = s_bcast[1];

        // Phase B: preds from smem, weighted squared diffs
        #pragma unroll
        for (int i = 0; i < V4; i++) {
            const int gi = (t + i * BLOCK) * 4;
            const float4 p = spred[t + i * BLOCK];
            const float d0 = p.x - l[i].x;
            const float d1 = p.y - l[i].y;
            const float d2 = p.z - l[i].z;
            const float d3 = p.w - l[i].w;
            const float w0 = (gi + 0 < first || gi + 0 > last) ? 2.0f : 1.0f;
            const float w1 = (gi + 1 < first || gi + 1 > last) ? 2.0f : 1.0f;
            const float w2 = (gi + 2 < first || gi + 2 > last) ? 2.0f : 1.0f;
            const float w3 = (gi + 3 < first || gi + 3 > last) ? 2.0f : 1.0f;
            wacc += w0 * d0 * d0 + w1 * d1 * d1 + w2 * d2 * d2 + w3 * d3 * d3;
        }

        __syncthreads();   // all threads done reading stage s
        if (t == 0 && k + D_STAGES < nk) {
            const long rid = bid + (long)(k + D_STAGES) * G;
            const uint32_t dst = smem_base + s * STAGE_BYTES;
            mbar_expect_tx(mbar[s], STAGE_BYTES);
            bulk_g2s(dst,             lab  + rid * H_HALF, ROW_BYTES, mbar[s]);
            bulk_g2s(dst + ROW_BYTES, pred + rid * H_HALF, ROW_BYTES, mbar[s]);
        }
    }

    // Block reduce wacc (deterministic)
    #pragma unroll
    for (int o = 16; o > 0; o >>= 1)
        wacc += __shfl_xor_sync(0xFFFFFFFFu, wacc, o);
    if (lid == 0) s_sum[wid] = wacc;
    __syncthreads();
    if (t == 0) {
        float v = 0.0f;
        #pragma unroll
        for (int w = 0; w < NWARP; w++) v += s_sum[w];
        g_partial[bid] = v;
        __threadfence();
        unsigned int done = atomicAdd(&g_counter, 1u);
        s_is_last = (done == G - 1) ? 1 : 0;
    }
    __syncthreads();

    if (s_is_last) {
        __threadfence();
        float facc = 0.0f;
        for (int i = t; i < G; i += BLOCK)
            facc += __ldcg(&g_partial[i]);   // fixed order -> deterministic
        #pragma unroll
        for (int o = 16; o > 0; o >>= 1)
            facc += __shfl_xor_sync(0xFFFFFFFFu, facc, o);
        if (lid == 0) s_sum[wid] = facc;
        __syncthreads();
        if (t == 0) {
            float v = 0.0f;
            #pragma unroll
            for (int w = 0; w < NWARP; w++) v += s_sum[w];
            out[0] = v * scale;
            g_counter = 0;   // reset for next graph replay
        }
    }
}

extern "C" void kernel_launch(void* const* d_in, const int* in_sizes, int n_in,
                              void* d_out, int out_size) {
    const float* pred = (const float*)d_in[0];
    const float* lab  = (const float*)d_in[1];
    float* out = (float*)d_out;

    const long n = in_sizes[0];            // total elements (B * N)
    const int total_rows = (int)(n / H_HALF);   // B * 2 half-rows
    const long B = total_rows / 2;
    const float scale = 1.0f / ((float)B * (float)H_HALF);

    // Idempotent, capture-legal; no static guards allowed in kernel_launch.
    cudaFuncSetAttribute(pulse_loss_kernel,
                         cudaFuncAttributeMaxDynamicSharedMemorySize,
                         D_STAGES * STAGE_BYTES);

    int grid = MAX_GRID;
    if (grid > total_rows) grid = total_rows;
    pulse_loss_kernel<<<grid, BLOCK, D_STAGES * STAGE_BYTES>>>(
        pred, lab, out, scale, total_rows);
}